// round 10
// baseline (speedup 1.0000x reference)
#include <cuda_runtime.h>
#include <cuda_fp16.h>
#include <cstdint>

// ============================================================================
// SimpleMACELayer — Round 9: fp16 mma.sync + ldmatrix + smem-compact cg +
// half2 A. 2 CTAs/SM. R8 skeleton (3 barriers/chunk).
// ============================================================================

#define EPB 128
#define NTHREADS 256
#define Q_TOTAL 99

__constant__ signed char cQP[Q_TOTAL] = {
    0, 1,1,1, 2,2,2,2,2, 3,3,3,3,3,3,3,
    4,4,4, 5, 6,6,6,6,6, 7,7,7, 8,8,8,8,8,8,8, 9,9,9,9,9,
    10,10,10,10,10, 11,11,11, 12,12,12,12,12,12,12, 13,
    14,14,14,14,14, 15,15,15, 16,16,16,16,16,16,16,
    17,17,17,17,17,17,17, 18,18,18,18,18, 19,19,19,
    20,20,20,20,20,20,20, 21, 22,22,22,22,22};
__constant__ signed char cQKG[Q_TOTAL] = {
    0, 1,2,3, 4,5,6,7,8, 9,10,11,12,13,14,15,
    1,2,3, 0, 4,5,6,7,8, 1,2,3, 9,10,11,12,13,14,15, 4,5,6,7,8,
    4,5,6,7,8, 1,2,3, 9,10,11,12,13,14,15, 0,
    4,5,6,7,8, 1,2,3, 9,10,11,12,13,14,15,
    9,10,11,12,13,14,15, 4,5,6,7,8, 1,2,3,
    9,10,11,12,13,14,15, 0, 4,5,6,7,8};
__constant__ signed char cQJ0[Q_TOTAL] = {
    0, 1,1,1, 4,4,4,4,4, 9,9,9,9,9,9,9,
    0,0,0, 1, 1,1,1,1,1, 4,4,4, 4,4,4,4,4,4,4, 9,9,9,9,9,
    0,0,0,0,0, 1,1,1, 1,1,1,1,1,1,1, 4,
    4,4,4,4,4, 9,9,9, 9,9,9,9,9,9,9,
    0,0,0,0,0,0,0, 1,1,1,1,1, 4,4,4,
    4,4,4,4,4,4,4, 9, 9,9,9,9,9};
__constant__ int cPSTART[5] = {0, 16, 40, 71, 99};

// per-q base into the compact cg array (7 slots per (q,ic), zero padded)
__device__ __forceinline__ int qcgBase(int q) {
    return q < 16 ? q * 7
         : q < 40 ? 112 + (q - 16) * 21
         : q < 71 ? 616 + (q - 40) * 35
                  : 1701 + (q - 71) * 49;
}
#define CGC_N 3073

// Fused weights, fp16, o'-major: g_Mh[q][o'][h]
__device__ __half g_Mh[Q_TOTAL * 4096];

__device__ __forceinline__ void mma16(float* c, const uint32_t* a,
                                      uint32_t b0, uint32_t b1) {
    asm volatile(
        "mma.sync.aligned.m16n8k16.row.col.f32.f16.f16.f32 "
        "{%0,%1,%2,%3}, {%4,%5,%6,%7}, {%8,%9}, {%0,%1,%2,%3};"
        : "+f"(c[0]), "+f"(c[1]), "+f"(c[2]), "+f"(c[3])
        : "r"(a[0]), "r"(a[1]), "r"(a[2]), "r"(a[3]), "r"(b0), "r"(b1));
}
__device__ __forceinline__ void ldmx4(uint32_t* r, uint32_t addr) {
    asm volatile(
        "ldmatrix.sync.aligned.m8n8.x4.shared.b16 {%0,%1,%2,%3}, [%4];"
        : "=r"(r[0]), "=r"(r[1]), "=r"(r[2]), "=r"(r[3]) : "r"(addr));
}
__device__ __forceinline__ uint32_t smem_u32(const void* p) {
    uint32_t a;
    asm("{ .reg .u64 t; cvta.to.shared.u64 t, %1; cvt.u32.u64 %0, t; }"
        : "=r"(a) : "l"(p));
    return a;
}

// ---------------------------------------------------------------------------
__global__ void build_M_kernel(const float* __restrict__ tw,
                               const float* __restrict__ wlin) {
    int q = blockIdx.x, p = cQP[q], kg = cQKG[q];
    __shared__ float twS[4096], wlS[4096];
    for (int i = threadIdx.x; i < 4096; i += blockDim.x) twS[i] = tw[p * 4096 + i];
    for (int i = threadIdx.x; i < 4096; i += blockDim.x) {
        int o = i >> 6, op = i & 63;
        wlS[o * 64 + op] = wlin[op * 1024 + o * 16 + kg];
    }
    __syncthreads();
    for (int r = threadIdx.x; r < 4096; r += blockDim.x) {
        int h = r >> 6, op = r & 63;
        float acc = 0.0f;
#pragma unroll 8
        for (int o = 0; o < 64; ++o) acc += twS[h * 64 + o] * wlS[o * 64 + op];
        g_Mh[q * 4096 + op * 64 + h] = __float2half_rn(acc);
    }
}

__global__ void init_out_kernel(float* __restrict__ out,
                                const float* __restrict__ b, int total) {
    int i = blockIdx.x * blockDim.x + threadIdx.x;
    if (i < total) out[i] = b[i & 63];
}

// ---------------------------------------------------------------------------
// SMEM layout (bytes):
//   sSrc half  [7][128][32]        0       57344
//   sU   half  [2][128][40]        57344   20480  (row 80B)
//   sM   half  [2][64][40]         77824   10240
//   sY   f32   [16][128]           88064    8192
//   sA   half2 [7][128]            96256    3584
//   sCgc f32   [3073]              99840   12292 (+pad)
//   sIdx i32   [2][128]            112144   1024
// total 113168 -> 2 CTAs/SM
#define U_OFF   57344
#define M_OFF   77824
#define Y_OFF   88064
#define A_OFF   96256
#define CGC_OFF 99840
#define IDX_OFF 112144
#define SMEM_TOTAL 113168

__global__ __launch_bounds__(NTHREADS, 2)
void edge_kernel(const float* __restrict__ nf, const float* __restrict__ ev,
                 const int* __restrict__ ei, const float* __restrict__ cg,
                 float* __restrict__ out, int E) {
    extern __shared__ char smx[];
    __half*  sSrc = (__half*)smx;
    __half*  sU   = (__half*)(smx + U_OFF);
    __half*  sM   = (__half*)(smx + M_OFF);
    float*   sY   = (float*)(smx + Y_OFF);
    __half2* sA2  = (__half2*)(smx + A_OFF);
    float*   sCgc = (float*)(smx + CGC_OFF);
    int*     sIdx = (int*)(smx + IDX_OFF);
    const int tid = threadIdx.x;
    const int e0 = blockIdx.x * EPB;
    const uint32_t sb = smem_u32(smx);

    // ---- prologue: compact cg table ----
    for (int i = tid; i < CGC_N; i += NTHREADS) {
        int q, rem;
        if (i < 112)        { q = i / 7;              rem = i % 7; }
        else if (i < 616)   { int t = i - 112;  q = 16 + t / 21; rem = t % 21; }
        else if (i < 1701)  { int t = i - 616;  q = 40 + t / 35; rem = t % 35; }
        else                { int t = i - 1701; q = 71 + t / 49; rem = t % 49; }
        int ic = rem / 7, jc = rem % 7;
        int g = (q < 16) ? 0 : (q < 40) ? 1 : (q < 71) ? 2 : 3;
        int j0 = cQJ0[q], kg = cQKG[q];
        int nj = (j0 == 0) ? 1 : (j0 == 1) ? 3 : (j0 == 4) ? 5 : 7;
        sCgc[i] = (jc < nj)
            ? __ldg(&cg[(g * g + ic) * 256 + (j0 + jc) * 16 + kg]) : 0.0f;
    }

    // ---- Y + indices ----
    if (tid < EPB) {
        int e = e0 + tid;
        if (e < E) {
            float x = ev[e * 3], y = ev[e * 3 + 1], z = ev[e * 3 + 2];
            float x2 = x * x, y2 = y * y, z2 = z * z;
            float Y[16];
            Y[0] = 0.28209479177387814f;
            Y[1] = 0.4886025119029199f * y;
            Y[2] = 0.4886025119029199f * z;
            Y[3] = 0.4886025119029199f * x;
            Y[4] = 1.0925484305920792f * x * y;
            Y[5] = 1.0925484305920792f * y * z;
            Y[6] = 0.31539156525252005f * (3.0f * z2 - 1.0f);
            Y[7] = 1.0925484305920792f * x * z;
            Y[8] = 0.5462742152960396f * (x2 - y2);
            Y[9] = 0.5900435899266435f * y * (3.0f * x2 - y2);
            Y[10] = 2.890611442640554f * x * y * z;
            Y[11] = 0.4570457994644658f * y * (5.0f * z2 - 1.0f);
            Y[12] = 0.3731763325901154f * z * (5.0f * z2 - 3.0f);
            Y[13] = 0.4570457994644658f * x * (5.0f * z2 - 1.0f);
            Y[14] = 1.445305721320277f * z * (x2 - y2);
            Y[15] = 0.5900435899266435f * x * (x2 - 3.0f * y2);
#pragma unroll
            for (int j = 0; j < 16; ++j) sY[j * EPB + tid] = Y[j];
            sIdx[tid] = ei[e];
            sIdx[EPB + tid] = ei[E + e];
        } else {
#pragma unroll
            for (int j = 0; j < 16; ++j) sY[j * EPB + tid] = 0.0f;
            sIdx[tid] = 0;
            sIdx[EPB + tid] = -1;
        }
    }

    const int lane = tid & 31, gid = lane >> 2, tig = lane & 3;
    const int wy = (tid >> 5) & 3;   // e-tile (4 x 32 rows)
    const int wx = tid >> 7;         // o'-half (2 x 32 cols)
    float acc[2][4][4];
#pragma unroll
    for (int mt = 0; mt < 2; ++mt)
#pragma unroll
        for (int nt = 0; nt < 4; ++nt)
#pragma unroll
            for (int r = 0; r < 4; ++r) acc[mt][nt][r] = 0.0f;

    // ldmatrix per-lane base addresses (bytes)
    const uint32_t aBase = sb + U_OFF +
        (uint32_t)((wy * 32 + (lane & 15)) * 80 + (lane >> 4) * 16);
    const uint32_t bBase = sb + M_OFF +
        (uint32_t)((wx * 32 + (lane & 7) + (lane >> 4) * 8) * 80 +
                   ((lane >> 3) & 1) * 16);
    __syncthreads();

    for (int g = 0; g < 4; ++g) {
        const int nc = 2 * g + 1;
        for (int hlf = 0; hlf < 2; ++hlf) {
            // ---- gather sSrc[ic][e][hh] ----
            for (int idx = tid; idx < EPB * 32; idx += NTHREADS) {
                int e = idx >> 5, hh = idx & 31;
                const float* base =
                    nf + (size_t)sIdx[e] * 1024 + (hlf * 32 + hh) * 16;
                __half* d = sSrc + e * 32 + hh;
                if (g == 0) {
                    d[0] = __float2half_rn(__ldg(base));
                } else if (g == 1) {
                    float4 v = __ldg((const float4*)base);
                    d[0] = __float2half_rn(v.y);
                    d[4096] = __float2half_rn(v.z);
                    d[8192] = __float2half_rn(v.w);
                } else if (g == 2) {
                    float4 v = __ldg((const float4*)(base + 4));
                    float s = __ldg(base + 8);
                    d[0] = __float2half_rn(v.x);
                    d[4096] = __float2half_rn(v.y);
                    d[8192] = __float2half_rn(v.z);
                    d[12288] = __float2half_rn(v.w);
                    d[16384] = __float2half_rn(s);
                } else {
                    float4 va = __ldg((const float4*)(base + 8));
                    float4 vb = __ldg((const float4*)(base + 12));
                    d[0] = __float2half_rn(va.y);
                    d[4096] = __float2half_rn(va.z);
                    d[8192] = __float2half_rn(va.w);
                    d[12288] = __float2half_rn(vb.x);
                    d[16384] = __float2half_rn(vb.y);
                    d[20480] = __float2half_rn(vb.z);
                    d[24576] = __float2half_rn(vb.w);
                }
            }
            __syncthreads();

            const int qend = cPSTART[g + 1];
            for (int qb = cPSTART[g]; qb < qend; qb += 2) {
                const int nqc = (qend - qb >= 2) ? 2 : 1;

                // ---- phase A: A-coeffs (fp32 -> half2) + M tile copy ----
                for (int idx = tid; idx < nc * EPB; idx += NTHREADS) {
                    int e = idx & 127, ic = idx >> 7;
                    float a01[2];
                    a01[1] = 0.0f;
                    for (int qq = 0; qq < nqc; ++qq) {
                        int q = qb + qq;
                        int j0 = cQJ0[q];
                        const float* cp = sCgc + qcgBase(q) + ic * 7;
                        float a = 0.0f;
#pragma unroll
                        for (int jc = 0; jc < 7; ++jc)
                            a += sY[(j0 + jc) * EPB + e] * cp[jc];
                        a01[qq] = a;
                    }
                    sA2[ic * EPB + e] = __floats2half2_rn(a01[0], a01[1]);
                }
                for (int idx = tid; idx < nqc * 256; idx += NTHREADS) {
                    int qq = idx >> 8, w = idx & 255;
                    int o = w >> 2, seg = w & 3;
                    uint4 v = *(const uint4*)(g_Mh + (qb + qq) * 4096 + o * 64 +
                                              hlf * 32 + seg * 8);
                    *(uint4*)(sM + qq * 2560 + o * 40 + seg * 8) = v;
                }
                __syncthreads();

                // ---- phase B: U tiles ----
                for (int idx = tid; idx < EPB * 8; idx += NTHREADS) {
                    int e = idx >> 3, hv = idx & 7;
                    float u0[4] = {0, 0, 0, 0}, u1[4] = {0, 0, 0, 0};
#pragma unroll
                    for (int ic = 0; ic < 7; ++ic)
                        if (ic < nc) {
                            uint2 sw = *(const uint2*)(sSrc + ic * 4096 +
                                                       e * 32 + hv * 4);
                            float2 f0 = __half22float2(*(__half2*)&sw.x);
                            float2 f1 = __half22float2(*(__half2*)&sw.y);
                            float2 a2 = __half22float2(sA2[ic * EPB + e]);
                            u0[0] += a2.x * f0.x; u0[1] += a2.x * f0.y;
                            u0[2] += a2.x * f1.x; u0[3] += a2.x * f1.y;
                            u1[0] += a2.y * f0.x; u1[1] += a2.y * f0.y;
                            u1[2] += a2.y * f1.x; u1[3] += a2.y * f1.y;
                        }
                    {
                        __half2 p0 = __floats2half2_rn(u0[0], u0[1]);
                        __half2 p1 = __floats2half2_rn(u0[2], u0[3]);
                        uint2 st = {*(uint32_t*)&p0, *(uint32_t*)&p1};
                        *(uint2*)(sU + e * 40 + hv * 4) = st;
                    }
                    if (nqc == 2) {
                        __half2 p0 = __floats2half2_rn(u1[0], u1[1]);
                        __half2 p1 = __floats2half2_rn(u1[2], u1[3]);
                        uint2 st = {*(uint32_t*)&p0, *(uint32_t*)&p1};
                        *(uint2*)(sU + 5120 + e * 40 + hv * 4) = st;
                    }
                }
                __syncthreads();

                // ---- mma phase: ldmatrix fragments, warp tile 32e x 32o' ----
                for (int qq = 0; qq < nqc; ++qq) {
                    uint32_t aq = aBase + qq * 10240;
                    uint32_t bq = bBase + qq * 5120;
#pragma unroll
                    for (int ks = 0; ks < 2; ++ks) {
                        uint32_t aF0[4], aF1[4], bF0[4], bF1[4];
                        ldmx4(aF0, aq + ks * 32);
                        ldmx4(aF1, aq + ks * 32 + 16 * 80);
                        ldmx4(bF0, bq + ks * 32);
                        ldmx4(bF1, bq + ks * 32 + 16 * 80);
                        mma16(acc[0][0], aF0, bF0[0], bF0[1]);
                        mma16(acc[0][1], aF0, bF0[2], bF0[3]);
                        mma16(acc[0][2], aF0, bF1[0], bF1[1]);
                        mma16(acc[0][3], aF0, bF1[2], bF1[3]);
                        mma16(acc[1][0], aF1, bF0[0], bF0[1]);
                        mma16(acc[1][1], aF1, bF0[2], bF0[3]);
                        mma16(acc[1][2], aF1, bF1[0], bF1[1]);
                        mma16(acc[1][3], aF1, bF1[2], bF1[3]);
                    }
                }
                __syncthreads();
            }
        }
    }

    // ---- epilogue: float2 atomics into out[dst] ----
#pragma unroll
    for (int mt = 0; mt < 2; ++mt)
#pragma unroll
        for (int r = 0; r < 2; ++r) {
            int e = wy * 32 + mt * 16 + gid + r * 8;
            int dst = sIdx[EPB + e];
            if (dst >= 0) {
                float* op = out + (size_t)dst * 64 + wx * 32 + 2 * tig;
#pragma unroll
                for (int nt = 0; nt < 4; ++nt) {
                    float2 v = make_float2(acc[mt][nt][r * 2],
                                           acc[mt][nt][r * 2 + 1]);
                    atomicAdd((float2*)(op + nt * 8), v);
                }
            }
        }
}

// ---------------------------------------------------------------------------
extern "C" void kernel_launch(void* const* d_in, const int* in_sizes, int n_in,
                              void* d_out, int out_size) {
    const float* nf = (const float*)d_in[0];
    const float* ev = (const float*)d_in[1];
    const int* ei = (const int*)d_in[2];
    const float* cg = (const float*)d_in[3];
    const float* tw = (const float*)d_in[4];
    const float* wlin = (const float*)d_in[5];
    const float* bl = (const float*)d_in[6];
    float* out = (float*)d_out;
    const int E = in_sizes[1] / 3;
    const int N = in_sizes[0] / 1024;

    cudaFuncSetAttribute(edge_kernel,
                         cudaFuncAttributeMaxDynamicSharedMemorySize, SMEM_TOTAL);
    build_M_kernel<<<Q_TOTAL, 256>>>(tw, wlin);
    init_out_kernel<<<(N * 64 + 255) / 256, 256>>>(out, bl, N * 64);
    edge_kernel<<<(E + EPB - 1) / EPB, NTHREADS, SMEM_TOTAL>>>(nf, ev, ei, cg, out, E);
}

// round 11
// speedup vs baseline: 1.3531x; 1.3531x over previous
#include <cuda_runtime.h>
#include <cuda_fp16.h>
#include <cstdint>

// ============================================================================
// SimpleMACELayer — Round 10: R8 skeleton (fp16 mma.sync m16n8k16), EPB=64,
// 4 CTAs/SM for 8 warps/SMSP latency hiding. Single-variable vs R8.
// ============================================================================

#define EPB 64
#define NTHREADS 256
#define Q_TOTAL 99

__constant__ signed char cQP[Q_TOTAL] = {
    0, 1,1,1, 2,2,2,2,2, 3,3,3,3,3,3,3,
    4,4,4, 5, 6,6,6,6,6, 7,7,7, 8,8,8,8,8,8,8, 9,9,9,9,9,
    10,10,10,10,10, 11,11,11, 12,12,12,12,12,12,12, 13,
    14,14,14,14,14, 15,15,15, 16,16,16,16,16,16,16,
    17,17,17,17,17,17,17, 18,18,18,18,18, 19,19,19,
    20,20,20,20,20,20,20, 21, 22,22,22,22,22};
__constant__ signed char cQKG[Q_TOTAL] = {
    0, 1,2,3, 4,5,6,7,8, 9,10,11,12,13,14,15,
    1,2,3, 0, 4,5,6,7,8, 1,2,3, 9,10,11,12,13,14,15, 4,5,6,7,8,
    4,5,6,7,8, 1,2,3, 9,10,11,12,13,14,15, 0,
    4,5,6,7,8, 1,2,3, 9,10,11,12,13,14,15,
    9,10,11,12,13,14,15, 4,5,6,7,8, 1,2,3,
    9,10,11,12,13,14,15, 0, 4,5,6,7,8};
__constant__ signed char cQJ0[Q_TOTAL] = {
    0, 1,1,1, 4,4,4,4,4, 9,9,9,9,9,9,9,
    0,0,0, 1, 1,1,1,1,1, 4,4,4, 4,4,4,4,4,4,4, 9,9,9,9,9,
    0,0,0,0,0, 1,1,1, 1,1,1,1,1,1,1, 4,
    4,4,4,4,4, 9,9,9, 9,9,9,9,9,9,9,
    0,0,0,0,0,0,0, 1,1,1,1,1, 4,4,4,
    4,4,4,4,4,4,4, 9, 9,9,9,9,9};
__constant__ int cPSTART[5] = {0, 16, 40, 71, 99};

// Fused weights, fp16, o'-major: g_Mh[q][o'][h]
__device__ __half g_Mh[Q_TOTAL * 4096];

__device__ __forceinline__ void mma16(float* c, const uint32_t* a,
                                      uint32_t b0, uint32_t b1) {
    asm volatile(
        "mma.sync.aligned.m16n8k16.row.col.f32.f16.f16.f32 "
        "{%0,%1,%2,%3}, {%4,%5,%6,%7}, {%8,%9}, {%0,%1,%2,%3};"
        : "+f"(c[0]), "+f"(c[1]), "+f"(c[2]), "+f"(c[3])
        : "r"(a[0]), "r"(a[1]), "r"(a[2]), "r"(a[3]), "r"(b0), "r"(b1));
}

// ---------------------------------------------------------------------------
__global__ void build_M_kernel(const float* __restrict__ tw,
                               const float* __restrict__ wlin) {
    int q = blockIdx.x, p = cQP[q], kg = cQKG[q];
    __shared__ float twS[4096], wlS[4096];
    for (int i = threadIdx.x; i < 4096; i += blockDim.x) twS[i] = tw[p * 4096 + i];
    for (int i = threadIdx.x; i < 4096; i += blockDim.x) {
        int o = i >> 6, op = i & 63;
        wlS[o * 64 + op] = wlin[op * 1024 + o * 16 + kg];
    }
    __syncthreads();
    for (int r = threadIdx.x; r < 4096; r += blockDim.x) {
        int h = r >> 6, op = r & 63;
        float acc = 0.0f;
#pragma unroll 8
        for (int o = 0; o < 64; ++o) acc += twS[h * 64 + o] * wlS[o * 64 + op];
        g_Mh[q * 4096 + op * 64 + h] = __float2half_rn(acc);
    }
}

__global__ void init_out_kernel(float* __restrict__ out,
                                const float* __restrict__ b, int total) {
    int i = blockIdx.x * blockDim.x + threadIdx.x;
    if (i < total) out[i] = b[i & 63];
}

// ---------------------------------------------------------------------------
// SMEM layout (bytes), EPB=64:
//   sSrc half [ic7][e64][hh32]         0     28672
//   sU   half [q2][e64][40]        28672     10240  (row 80B)
//   sM   half [q2][o64][40]        38912     10240
//   sY   f32  [j16][e64]           49152      4096
//   sA   f32  [q2*7][e64]          53248      3584
//   sIdx i32  [2][64]              56832       512
// total 57344 B -> 4 CTAs/SM (229376 <= 233472)
#define U_OFF   28672
#define M_OFF   38912
#define Y_OFF   49152
#define A_OFF   53248
#define IDX_OFF 56832
#define SMEM_TOTAL 57344

#define U_STRIDE 40   // halves
#define M_STRIDE 40   // halves
#define U_QSZ (EPB * U_STRIDE)   // 2560 halves
#define M_QSZ (64 * M_STRIDE)    // 2560 halves

__global__ __launch_bounds__(NTHREADS, 4)
void edge_kernel(const float* __restrict__ nf, const float* __restrict__ ev,
                 const int* __restrict__ ei, const float* __restrict__ cg,
                 float* __restrict__ out, int E) {
    extern __shared__ char smx[];
    __half* sSrc = (__half*)smx;
    __half* sU = (__half*)(smx + U_OFF);
    __half* sM = (__half*)(smx + M_OFF);
    float* sY = (float*)(smx + Y_OFF);
    float* sA = (float*)(smx + A_OFF);
    int* sIdx = (int*)(smx + IDX_OFF);
    const int tid = threadIdx.x;
    const int e0 = blockIdx.x * EPB;

    // ---- Y + indices ----
    if (tid < EPB) {
        int e = e0 + tid;
        if (e < E) {
            float x = ev[e * 3], y = ev[e * 3 + 1], z = ev[e * 3 + 2];
            float x2 = x * x, y2 = y * y, z2 = z * z;
            float Y[16];
            Y[0] = 0.28209479177387814f;
            Y[1] = 0.4886025119029199f * y;
            Y[2] = 0.4886025119029199f * z;
            Y[3] = 0.4886025119029199f * x;
            Y[4] = 1.0925484305920792f * x * y;
            Y[5] = 1.0925484305920792f * y * z;
            Y[6] = 0.31539156525252005f * (3.0f * z2 - 1.0f);
            Y[7] = 1.0925484305920792f * x * z;
            Y[8] = 0.5462742152960396f * (x2 - y2);
            Y[9] = 0.5900435899266435f * y * (3.0f * x2 - y2);
            Y[10] = 2.890611442640554f * x * y * z;
            Y[11] = 0.4570457994644658f * y * (5.0f * z2 - 1.0f);
            Y[12] = 0.3731763325901154f * z * (5.0f * z2 - 3.0f);
            Y[13] = 0.4570457994644658f * x * (5.0f * z2 - 1.0f);
            Y[14] = 1.445305721320277f * z * (x2 - y2);
            Y[15] = 0.5900435899266435f * x * (x2 - 3.0f * y2);
#pragma unroll
            for (int j = 0; j < 16; ++j) sY[j * EPB + tid] = Y[j];
            sIdx[tid] = ei[e];
            sIdx[EPB + tid] = ei[E + e];
        } else {
#pragma unroll
            for (int j = 0; j < 16; ++j) sY[j * EPB + tid] = 0.0f;
            sIdx[tid] = 0;
            sIdx[EPB + tid] = -1;
        }
    }

    const int lane = tid & 31, gid = lane >> 2, tig = lane & 3;
    const int wy = (tid >> 5) & 3;   // e-tile (4 x 16 rows)
    const int wx = tid >> 7;         // o'-half (2 x 32 cols)
    float acc[4][4];
#pragma unroll
    for (int nt = 0; nt < 4; ++nt)
#pragma unroll
        for (int r = 0; r < 4; ++r) acc[nt][r] = 0.0f;
    __syncthreads();

    for (int g = 0; g < 4; ++g) {
        const int nc = 2 * g + 1, i0 = g * g;
        for (int hlf = 0; hlf < 2; ++hlf) {
            // ---- gather sSrc[ic][e][hh] (vectorized over irreps) ----
            for (int idx = tid; idx < EPB * 32; idx += NTHREADS) {
                int e = idx >> 5, hh = idx & 31;
                const float* base =
                    nf + (size_t)sIdx[e] * 1024 + (hlf * 32 + hh) * 16;
                __half* d = sSrc + e * 32 + hh;  // + ic*2048
                if (g == 0) {
                    d[0] = __float2half_rn(__ldg(base));
                } else if (g == 1) {
                    float4 v = __ldg((const float4*)base);
                    d[0] = __float2half_rn(v.y);
                    d[2048] = __float2half_rn(v.z);
                    d[4096] = __float2half_rn(v.w);
                } else if (g == 2) {
                    float4 v = __ldg((const float4*)(base + 4));
                    float s = __ldg(base + 8);
                    d[0] = __float2half_rn(v.x);
                    d[2048] = __float2half_rn(v.y);
                    d[4096] = __float2half_rn(v.z);
                    d[6144] = __float2half_rn(v.w);
                    d[8192] = __float2half_rn(s);
                } else {
                    float4 va = __ldg((const float4*)(base + 8));
                    float4 vb = __ldg((const float4*)(base + 12));
                    d[0] = __float2half_rn(va.y);
                    d[2048] = __float2half_rn(va.z);
                    d[4096] = __float2half_rn(va.w);
                    d[6144] = __float2half_rn(vb.x);
                    d[8192] = __float2half_rn(vb.y);
                    d[10240] = __float2half_rn(vb.z);
                    d[12288] = __float2half_rn(vb.w);
                }
            }
            __syncthreads();

            const int qend = cPSTART[g + 1];
            for (int qb = cPSTART[g]; qb < qend; qb += 2) {
                const int nqc = (qend - qb >= 2) ? 2 : 1;

                // ---- phase A: A-coeffs (fp32) + M tile copy (fp16) ----
                for (int idx = tid; idx < nqc * nc * EPB; idx += NTHREADS) {
                    int e = idx & 63, r = idx >> 6;
                    int ic = r % nc, qq = r / nc, q = qb + qq;
                    int j0 = cQJ0[q], kg = cQKG[q];
                    int nj = (j0 == 0) ? 1 : (j0 == 1) ? 3 : (j0 == 4) ? 5 : 7;
                    const float* cgp = cg + (i0 + ic) * 256 + j0 * 16 + kg;
                    float a = 0.0f;
#pragma unroll
                    for (int jc = 0; jc < 7; ++jc)
                        if (jc < nj) a += sY[(j0 + jc) * EPB + e] * __ldg(cgp + jc * 16);
                    sA[(qq * 7 + ic) * EPB + e] = a;
                }
                for (int idx = tid; idx < nqc * 256; idx += NTHREADS) {
                    int qq = idx >> 8, w = idx & 255;
                    int o = w >> 2, seg = w & 3;
                    uint4 v = *(const uint4*)(g_Mh + (qb + qq) * 4096 + o * 64 +
                                              hlf * 32 + seg * 8);
                    *(uint4*)(sM + qq * M_QSZ + o * M_STRIDE + seg * 8) = v;
                }
                __syncthreads();

                // ---- phase B: U tiles (fp32 math, fp16 store) ----
                for (int idx = tid; idx < EPB * 8; idx += NTHREADS) {
                    int e = idx >> 3, hv = idx & 7;
                    float u0[4] = {0, 0, 0, 0}, u1[4] = {0, 0, 0, 0};
#pragma unroll
                    for (int ic = 0; ic < 7; ++ic)
                        if (ic < nc) {
                            uint2 sw = *(const uint2*)(sSrc + ic * 2048 +
                                                       e * 32 + hv * 4);
                            float2 f0 = __half22float2(*(__half2*)&sw.x);
                            float2 f1 = __half22float2(*(__half2*)&sw.y);
                            float a0 = sA[ic * EPB + e];
                            u0[0] += a0 * f0.x; u0[1] += a0 * f0.y;
                            u0[2] += a0 * f1.x; u0[3] += a0 * f1.y;
                            if (nqc == 2) {
                                float a1 = sA[(7 + ic) * EPB + e];
                                u1[0] += a1 * f0.x; u1[1] += a1 * f0.y;
                                u1[2] += a1 * f1.x; u1[3] += a1 * f1.y;
                            }
                        }
                    {
                        __half2 p0 = __floats2half2_rn(u0[0], u0[1]);
                        __half2 p1 = __floats2half2_rn(u0[2], u0[3]);
                        uint2 st = {*(uint32_t*)&p0, *(uint32_t*)&p1};
                        *(uint2*)(sU + e * U_STRIDE + hv * 4) = st;
                    }
                    if (nqc == 2) {
                        __half2 p0 = __floats2half2_rn(u1[0], u1[1]);
                        __half2 p1 = __floats2half2_rn(u1[2], u1[3]);
                        uint2 st = {*(uint32_t*)&p0, *(uint32_t*)&p1};
                        *(uint2*)(sU + U_QSZ + e * U_STRIDE + hv * 4) = st;
                    }
                }
                __syncthreads();

                // ---- mma phase: warp tile 16e x 32o', K = 32 per q ----
                for (int qq = 0; qq < nqc; ++qq) {
                    const __half* Ub = sU + qq * U_QSZ;
                    const __half* Mb = sM + qq * M_QSZ;
#pragma unroll
                    for (int ks = 0; ks < 2; ++ks) {
                        const int k0 = ks * 16 + 2 * tig;
                        uint32_t a[4];
                        {
                            const __half* up =
                                Ub + (wy * 16 + gid) * U_STRIDE + k0;
                            a[0] = *(const uint32_t*)(up);
                            a[1] = *(const uint32_t*)(up + 8 * U_STRIDE);
                            a[2] = *(const uint32_t*)(up + 8);
                            a[3] = *(const uint32_t*)(up + 8 * U_STRIDE + 8);
                        }
#pragma unroll
                        for (int nt = 0; nt < 4; ++nt) {
                            const __half* mp =
                                Mb + (wx * 32 + nt * 8 + gid) * M_STRIDE + k0;
                            uint32_t b0 = *(const uint32_t*)(mp);
                            uint32_t b1 = *(const uint32_t*)(mp + 8);
                            mma16(acc[nt], a, b0, b1);
                        }
                    }
                }
                __syncthreads();
            }
        }
    }

    // ---- epilogue: float2 atomics into out[dst] ----
#pragma unroll
    for (int r = 0; r < 2; ++r) {
        int e = wy * 16 + gid + r * 8;
        int dst = sIdx[EPB + e];
        if (dst >= 0) {
            float* op = out + (size_t)dst * 64 + wx * 32 + 2 * tig;
#pragma unroll
            for (int nt = 0; nt < 4; ++nt) {
                float2 v = make_float2(acc[nt][r * 2], acc[nt][r * 2 + 1]);
                atomicAdd((float2*)(op + nt * 8), v);
            }
        }
    }
}

// ---------------------------------------------------------------------------
extern "C" void kernel_launch(void* const* d_in, const int* in_sizes, int n_in,
                              void* d_out, int out_size) {
    const float* nf = (const float*)d_in[0];
    const float* ev = (const float*)d_in[1];
    const int* ei = (const int*)d_in[2];
    const float* cg = (const float*)d_in[3];
    const float* tw = (const float*)d_in[4];
    const float* wlin = (const float*)d_in[5];
    const float* bl = (const float*)d_in[6];
    float* out = (float*)d_out;
    const int E = in_sizes[1] / 3;
    const int N = in_sizes[0] / 1024;

    cudaFuncSetAttribute(edge_kernel,
                         cudaFuncAttributeMaxDynamicSharedMemorySize, SMEM_TOTAL);
    build_M_kernel<<<Q_TOTAL, 256>>>(tw, wlin);
    init_out_kernel<<<(N * 64 + 255) / 256, 256>>>(out, bl, N * 64);
    edge_kernel<<<(E + EPB - 1) / EPB, NTHREADS, SMEM_TOTAL>>>(nf, ev, ei, cg, out, E);
}

// round 12
// speedup vs baseline: 1.4422x; 1.0659x over previous
#include <cuda_runtime.h>
#include <cuda_fp16.h>
#include <cstdint>

// ============================================================================
// SimpleMACELayer — Round 11: R10 + q-split warp mapping (B-frag traffic /2).
// EPB=64, 4 CTAs/SM, fp16 mma.sync m16n8k16. warp=(qq,wx,wy2), tile 32ex32o'.
// Epilogue: cross-q smem reduction, then float2 atomics.
// ============================================================================

#define EPB 64
#define NTHREADS 256
#define Q_TOTAL 99

__constant__ signed char cQP[Q_TOTAL] = {
    0, 1,1,1, 2,2,2,2,2, 3,3,3,3,3,3,3,
    4,4,4, 5, 6,6,6,6,6, 7,7,7, 8,8,8,8,8,8,8, 9,9,9,9,9,
    10,10,10,10,10, 11,11,11, 12,12,12,12,12,12,12, 13,
    14,14,14,14,14, 15,15,15, 16,16,16,16,16,16,16,
    17,17,17,17,17,17,17, 18,18,18,18,18, 19,19,19,
    20,20,20,20,20,20,20, 21, 22,22,22,22,22};
__constant__ signed char cQKG[Q_TOTAL] = {
    0, 1,2,3, 4,5,6,7,8, 9,10,11,12,13,14,15,
    1,2,3, 0, 4,5,6,7,8, 1,2,3, 9,10,11,12,13,14,15, 4,5,6,7,8,
    4,5,6,7,8, 1,2,3, 9,10,11,12,13,14,15, 0,
    4,5,6,7,8, 1,2,3, 9,10,11,12,13,14,15,
    9,10,11,12,13,14,15, 4,5,6,7,8, 1,2,3,
    9,10,11,12,13,14,15, 0, 4,5,6,7,8};
__constant__ signed char cQJ0[Q_TOTAL] = {
    0, 1,1,1, 4,4,4,4,4, 9,9,9,9,9,9,9,
    0,0,0, 1, 1,1,1,1,1, 4,4,4, 4,4,4,4,4,4,4, 9,9,9,9,9,
    0,0,0,0,0, 1,1,1, 1,1,1,1,1,1,1, 4,
    4,4,4,4,4, 9,9,9, 9,9,9,9,9,9,9,
    0,0,0,0,0,0,0, 1,1,1,1,1, 4,4,4,
    4,4,4,4,4,4,4, 9, 9,9,9,9,9};
__constant__ int cPSTART[5] = {0, 16, 40, 71, 99};

// Fused weights, fp16, o'-major: g_Mh[q][o'][h]
__device__ __half g_Mh[Q_TOTAL * 4096];

__device__ __forceinline__ void mma16(float* c, const uint32_t* a,
                                      uint32_t b0, uint32_t b1) {
    asm volatile(
        "mma.sync.aligned.m16n8k16.row.col.f32.f16.f16.f32 "
        "{%0,%1,%2,%3}, {%4,%5,%6,%7}, {%8,%9}, {%0,%1,%2,%3};"
        : "+f"(c[0]), "+f"(c[1]), "+f"(c[2]), "+f"(c[3])
        : "r"(a[0]), "r"(a[1]), "r"(a[2]), "r"(a[3]), "r"(b0), "r"(b1));
}

// ---------------------------------------------------------------------------
__global__ void build_M_kernel(const float* __restrict__ tw,
                               const float* __restrict__ wlin) {
    int q = blockIdx.x, p = cQP[q], kg = cQKG[q];
    __shared__ float twS[4096], wlS[4096];
    for (int i = threadIdx.x; i < 4096; i += blockDim.x) twS[i] = tw[p * 4096 + i];
    for (int i = threadIdx.x; i < 4096; i += blockDim.x) {
        int o = i >> 6, op = i & 63;
        wlS[o * 64 + op] = wlin[op * 1024 + o * 16 + kg];
    }
    __syncthreads();
    for (int r = threadIdx.x; r < 4096; r += blockDim.x) {
        int h = r >> 6, op = r & 63;
        float acc = 0.0f;
#pragma unroll 8
        for (int o = 0; o < 64; ++o) acc += twS[h * 64 + o] * wlS[o * 64 + op];
        g_Mh[q * 4096 + op * 64 + h] = __float2half_rn(acc);
    }
}

__global__ void init_out_kernel(float* __restrict__ out,
                                const float* __restrict__ b, int total) {
    int i = blockIdx.x * blockDim.x + threadIdx.x;
    if (i < total) out[i] = b[i & 63];
}

// ---------------------------------------------------------------------------
// SMEM layout (bytes), EPB=64 (identical to R10):
//   sSrc half [ic7][e64][hh32]         0     28672   (reused as sRed f32 16KB)
//   sU   half [q2][e64][40]        28672     10240
//   sM   half [q2][o64][40]        38912     10240
//   sY   f32  [j16][e64]           49152      4096
//   sA   f32  [q2*7][e64]          53248      3584
//   sIdx i32  [2][64]              56832       512
// total 57344 B -> 4 CTAs/SM
#define U_OFF   28672
#define M_OFF   38912
#define Y_OFF   49152
#define A_OFF   53248
#define IDX_OFF 56832
#define SMEM_TOTAL 57344

#define U_STRIDE 40
#define M_STRIDE 40
#define U_QSZ (EPB * U_STRIDE)   // 2560 halves
#define M_QSZ (64 * M_STRIDE)    // 2560 halves

__global__ __launch_bounds__(NTHREADS, 4)
void edge_kernel(const float* __restrict__ nf, const float* __restrict__ ev,
                 const int* __restrict__ ei, const float* __restrict__ cg,
                 float* __restrict__ out, int E) {
    extern __shared__ char smx[];
    __half* sSrc = (__half*)smx;
    __half* sU = (__half*)(smx + U_OFF);
    __half* sM = (__half*)(smx + M_OFF);
    float* sY = (float*)(smx + Y_OFF);
    float* sA = (float*)(smx + A_OFF);
    int* sIdx = (int*)(smx + IDX_OFF);
    const int tid = threadIdx.x;
    const int e0 = blockIdx.x * EPB;

    // ---- Y + indices ----
    if (tid < EPB) {
        int e = e0 + tid;
        if (e < E) {
            float x = ev[e * 3], y = ev[e * 3 + 1], z = ev[e * 3 + 2];
            float x2 = x * x, y2 = y * y, z2 = z * z;
            float Y[16];
            Y[0] = 0.28209479177387814f;
            Y[1] = 0.4886025119029199f * y;
            Y[2] = 0.4886025119029199f * z;
            Y[3] = 0.4886025119029199f * x;
            Y[4] = 1.0925484305920792f * x * y;
            Y[5] = 1.0925484305920792f * y * z;
            Y[6] = 0.31539156525252005f * (3.0f * z2 - 1.0f);
            Y[7] = 1.0925484305920792f * x * z;
            Y[8] = 0.5462742152960396f * (x2 - y2);
            Y[9] = 0.5900435899266435f * y * (3.0f * x2 - y2);
            Y[10] = 2.890611442640554f * x * y * z;
            Y[11] = 0.4570457994644658f * y * (5.0f * z2 - 1.0f);
            Y[12] = 0.3731763325901154f * z * (5.0f * z2 - 3.0f);
            Y[13] = 0.4570457994644658f * x * (5.0f * z2 - 1.0f);
            Y[14] = 1.445305721320277f * z * (x2 - y2);
            Y[15] = 0.5900435899266435f * x * (x2 - 3.0f * y2);
#pragma unroll
            for (int j = 0; j < 16; ++j) sY[j * EPB + tid] = Y[j];
            sIdx[tid] = ei[e];
            sIdx[EPB + tid] = ei[E + e];
        } else {
#pragma unroll
            for (int j = 0; j < 16; ++j) sY[j * EPB + tid] = 0.0f;
            sIdx[tid] = 0;
            sIdx[EPB + tid] = -1;
        }
    }

    // q-split warp mapping: warp = (qq, wx, wy2)
    const int lane = tid & 31, gid = lane >> 2, tig = lane & 3;
    const int wid = tid >> 5;
    const int qq = wid & 1;          // which q of the chunk pair
    const int wx = (wid >> 1) & 1;   // o'-half (2 x 32)
    const int wy2 = wid >> 2;        // e-half (2 x 32)
    float acc[2][4][4];
#pragma unroll
    for (int mt = 0; mt < 2; ++mt)
#pragma unroll
        for (int nt = 0; nt < 4; ++nt)
#pragma unroll
            for (int r = 0; r < 4; ++r) acc[mt][nt][r] = 0.0f;
    __syncthreads();

    for (int g = 0; g < 4; ++g) {
        const int nc = 2 * g + 1, i0 = g * g;
        for (int hlf = 0; hlf < 2; ++hlf) {
            // ---- gather sSrc[ic][e][hh] (vectorized over irreps) ----
            for (int idx = tid; idx < EPB * 32; idx += NTHREADS) {
                int e = idx >> 5, hh = idx & 31;
                const float* base =
                    nf + (size_t)sIdx[e] * 1024 + (hlf * 32 + hh) * 16;
                __half* d = sSrc + e * 32 + hh;  // + ic*2048
                if (g == 0) {
                    d[0] = __float2half_rn(__ldg(base));
                } else if (g == 1) {
                    float4 v = __ldg((const float4*)base);
                    d[0] = __float2half_rn(v.y);
                    d[2048] = __float2half_rn(v.z);
                    d[4096] = __float2half_rn(v.w);
                } else if (g == 2) {
                    float4 v = __ldg((const float4*)(base + 4));
                    float s = __ldg(base + 8);
                    d[0] = __float2half_rn(v.x);
                    d[2048] = __float2half_rn(v.y);
                    d[4096] = __float2half_rn(v.z);
                    d[6144] = __float2half_rn(v.w);
                    d[8192] = __float2half_rn(s);
                } else {
                    float4 va = __ldg((const float4*)(base + 8));
                    float4 vb = __ldg((const float4*)(base + 12));
                    d[0] = __float2half_rn(va.y);
                    d[2048] = __float2half_rn(va.z);
                    d[4096] = __float2half_rn(va.w);
                    d[6144] = __float2half_rn(vb.x);
                    d[8192] = __float2half_rn(vb.y);
                    d[10240] = __float2half_rn(vb.z);
                    d[12288] = __float2half_rn(vb.w);
                }
            }
            __syncthreads();

            const int qend = cPSTART[g + 1];
            for (int qb = cPSTART[g]; qb < qend; qb += 2) {
                const int nqc = (qend - qb >= 2) ? 2 : 1;

                // ---- phase A: A-coeffs (fp32) + M tile copy (fp16) ----
                for (int idx = tid; idx < nqc * nc * EPB; idx += NTHREADS) {
                    int e = idx & 63, r = idx >> 6;
                    int ic = r % nc, qi = r / nc, q = qb + qi;
                    int j0 = cQJ0[q], kg = cQKG[q];
                    int nj = (j0 == 0) ? 1 : (j0 == 1) ? 3 : (j0 == 4) ? 5 : 7;
                    const float* cgp = cg + (i0 + ic) * 256 + j0 * 16 + kg;
                    float a = 0.0f;
#pragma unroll
                    for (int jc = 0; jc < 7; ++jc)
                        if (jc < nj) a += sY[(j0 + jc) * EPB + e] * __ldg(cgp + jc * 16);
                    sA[(qi * 7 + ic) * EPB + e] = a;
                }
                for (int idx = tid; idx < nqc * 256; idx += NTHREADS) {
                    int qi = idx >> 8, w = idx & 255;
                    int o = w >> 2, seg = w & 3;
                    uint4 v = *(const uint4*)(g_Mh + (qb + qi) * 4096 + o * 64 +
                                              hlf * 32 + seg * 8);
                    *(uint4*)(sM + qi * M_QSZ + o * M_STRIDE + seg * 8) = v;
                }
                __syncthreads();

                // ---- phase B: U tiles (fp32 math, fp16 store) ----
                for (int idx = tid; idx < EPB * 8; idx += NTHREADS) {
                    int e = idx >> 3, hv = idx & 7;
                    float u0[4] = {0, 0, 0, 0}, u1[4] = {0, 0, 0, 0};
#pragma unroll
                    for (int ic = 0; ic < 7; ++ic)
                        if (ic < nc) {
                            uint2 sw = *(const uint2*)(sSrc + ic * 2048 +
                                                       e * 32 + hv * 4);
                            float2 f0 = __half22float2(*(__half2*)&sw.x);
                            float2 f1 = __half22float2(*(__half2*)&sw.y);
                            float a0 = sA[ic * EPB + e];
                            u0[0] += a0 * f0.x; u0[1] += a0 * f0.y;
                            u0[2] += a0 * f1.x; u0[3] += a0 * f1.y;
                            if (nqc == 2) {
                                float a1 = sA[(7 + ic) * EPB + e];
                                u1[0] += a1 * f0.x; u1[1] += a1 * f0.y;
                                u1[2] += a1 * f1.x; u1[3] += a1 * f1.y;
                            }
                        }
                    {
                        __half2 p0 = __floats2half2_rn(u0[0], u0[1]);
                        __half2 p1 = __floats2half2_rn(u0[2], u0[3]);
                        uint2 st = {*(uint32_t*)&p0, *(uint32_t*)&p1};
                        *(uint2*)(sU + e * U_STRIDE + hv * 4) = st;
                    }
                    if (nqc == 2) {
                        __half2 p0 = __floats2half2_rn(u1[0], u1[1]);
                        __half2 p1 = __floats2half2_rn(u1[2], u1[3]);
                        uint2 st = {*(uint32_t*)&p0, *(uint32_t*)&p1};
                        *(uint2*)(sU + U_QSZ + e * U_STRIDE + hv * 4) = st;
                    }
                }
                __syncthreads();

                // ---- mma phase: warp owns ONE q, tile 32e x 32o' ----
                if (qq < nqc) {
                    const __half* Ub = sU + qq * U_QSZ;
                    const __half* Mb = sM + qq * M_QSZ;
#pragma unroll
                    for (int ks = 0; ks < 2; ++ks) {
                        const int k0 = ks * 16 + 2 * tig;
                        uint32_t a[2][4];
#pragma unroll
                        for (int mt = 0; mt < 2; ++mt) {
                            const __half* up =
                                Ub + (wy2 * 32 + mt * 16 + gid) * U_STRIDE + k0;
                            a[mt][0] = *(const uint32_t*)(up);
                            a[mt][1] = *(const uint32_t*)(up + 8 * U_STRIDE);
                            a[mt][2] = *(const uint32_t*)(up + 8);
                            a[mt][3] = *(const uint32_t*)(up + 8 * U_STRIDE + 8);
                        }
#pragma unroll
                        for (int nt = 0; nt < 4; ++nt) {
                            const __half* mp =
                                Mb + (wx * 32 + nt * 8 + gid) * M_STRIDE + k0;
                            uint32_t b0 = *(const uint32_t*)(mp);
                            uint32_t b1 = *(const uint32_t*)(mp + 8);
                            mma16(acc[0][nt], a[0], b0, b1);
                            mma16(acc[1][nt], a[1], b0, b1);
                        }
                    }
                }
                __syncthreads();
            }
        }
    }

    // ---- cross-q reduction: qq=1 warps dump acc, qq=0 warps add ----
    {
        float* sRed = (float*)smx;   // 4 tiles x 32x32 f32 = 16KB (sSrc dead)
        float* tile = sRed + (wy2 * 2 + wx) * 1024;
        if (qq == 1) {
#pragma unroll
            for (int mt = 0; mt < 2; ++mt)
#pragma unroll
                for (int nt = 0; nt < 4; ++nt)
#pragma unroll
                    for (int r = 0; r < 4; ++r) {
                        int row = mt * 16 + gid + (r >> 1) * 8;
                        int col = nt * 8 + tig * 2 + (r & 1);
                        tile[row * 32 + col] = acc[mt][nt][r];
                    }
        }
        __syncthreads();
        if (qq == 0) {
#pragma unroll
            for (int mt = 0; mt < 2; ++mt)
#pragma unroll
                for (int nt = 0; nt < 4; ++nt)
#pragma unroll
                    for (int r = 0; r < 4; ++r) {
                        int row = mt * 16 + gid + (r >> 1) * 8;
                        int col = nt * 8 + tig * 2 + (r & 1);
                        acc[mt][nt][r] += tile[row * 32 + col];
                    }
            // ---- epilogue: float2 atomics into out[dst] ----
#pragma unroll
            for (int mt = 0; mt < 2; ++mt)
#pragma unroll
                for (int r = 0; r < 2; ++r) {
                    int e = wy2 * 32 + mt * 16 + gid + r * 8;
                    int dst = sIdx[EPB + e];
                    if (dst >= 0) {
                        float* op = out + (size_t)dst * 64 + wx * 32 + 2 * tig;
#pragma unroll
                        for (int nt = 0; nt < 4; ++nt) {
                            float2 v = make_float2(acc[mt][nt][r * 2],
                                                   acc[mt][nt][r * 2 + 1]);
                            atomicAdd((float2*)(op + nt * 8), v);
                        }
                    }
                }
        }
    }
}

// ---------------------------------------------------------------------------
extern "C" void kernel_launch(void* const* d_in, const int* in_sizes, int n_in,
                              void* d_out, int out_size) {
    const float* nf = (const float*)d_in[0];
    const float* ev = (const float*)d_in[1];
    const int* ei = (const int*)d_in[2];
    const float* cg = (const float*)d_in[3];
    const float* tw = (const float*)d_in[4];
    const float* wlin = (const float*)d_in[5];
    const float* bl = (const float*)d_in[6];
    float* out = (float*)d_out;
    const int E = in_sizes[1] / 3;
    const int N = in_sizes[0] / 1024;

    cudaFuncSetAttribute(edge_kernel,
                         cudaFuncAttributeMaxDynamicSharedMemorySize, SMEM_TOTAL);
    build_M_kernel<<<Q_TOTAL, 256>>>(tw, wlin);
    init_out_kernel<<<(N * 64 + 255) / 256, 256>>>(out, bl, N * 64);
    edge_kernel<<<(E + EPB - 1) / EPB, NTHREADS, SMEM_TOTAL>>>(nf, ev, ei, cg, out, E);
}

// round 13
// speedup vs baseline: 1.4503x; 1.0056x over previous
#include <cuda_runtime.h>
#include <cuda_fp16.h>
#include <cstdint>

// ============================================================================
// SimpleMACELayer — Round 12: R11 + ldmatrix.x4 fragment loads (+ sA
// interleave). EPB=64, 4 CTAs/SM, fp16 mma.sync m16n8k16, q-split warps.
// ============================================================================

#define EPB 64
#define NTHREADS 256
#define Q_TOTAL 99

__constant__ signed char cQP[Q_TOTAL] = {
    0, 1,1,1, 2,2,2,2,2, 3,3,3,3,3,3,3,
    4,4,4, 5, 6,6,6,6,6, 7,7,7, 8,8,8,8,8,8,8, 9,9,9,9,9,
    10,10,10,10,10, 11,11,11, 12,12,12,12,12,12,12, 13,
    14,14,14,14,14, 15,15,15, 16,16,16,16,16,16,16,
    17,17,17,17,17,17,17, 18,18,18,18,18, 19,19,19,
    20,20,20,20,20,20,20, 21, 22,22,22,22,22};
__constant__ signed char cQKG[Q_TOTAL] = {
    0, 1,2,3, 4,5,6,7,8, 9,10,11,12,13,14,15,
    1,2,3, 0, 4,5,6,7,8, 1,2,3, 9,10,11,12,13,14,15, 4,5,6,7,8,
    4,5,6,7,8, 1,2,3, 9,10,11,12,13,14,15, 0,
    4,5,6,7,8, 1,2,3, 9,10,11,12,13,14,15,
    9,10,11,12,13,14,15, 4,5,6,7,8, 1,2,3,
    9,10,11,12,13,14,15, 0, 4,5,6,7,8};
__constant__ signed char cQJ0[Q_TOTAL] = {
    0, 1,1,1, 4,4,4,4,4, 9,9,9,9,9,9,9,
    0,0,0, 1, 1,1,1,1,1, 4,4,4, 4,4,4,4,4,4,4, 9,9,9,9,9,
    0,0,0,0,0, 1,1,1, 1,1,1,1,1,1,1, 4,
    4,4,4,4,4, 9,9,9, 9,9,9,9,9,9,9,
    0,0,0,0,0,0,0, 1,1,1,1,1, 4,4,4,
    4,4,4,4,4,4,4, 9, 9,9,9,9,9};
__constant__ int cPSTART[5] = {0, 16, 40, 71, 99};

// Fused weights, fp16, o'-major: g_Mh[q][o'][h]
__device__ __half g_Mh[Q_TOTAL * 4096];

__device__ __forceinline__ void mma16(float* c, const uint32_t* a,
                                      uint32_t b0, uint32_t b1) {
    asm volatile(
        "mma.sync.aligned.m16n8k16.row.col.f32.f16.f16.f32 "
        "{%0,%1,%2,%3}, {%4,%5,%6,%7}, {%8,%9}, {%0,%1,%2,%3};"
        : "+f"(c[0]), "+f"(c[1]), "+f"(c[2]), "+f"(c[3])
        : "r"(a[0]), "r"(a[1]), "r"(a[2]), "r"(a[3]), "r"(b0), "r"(b1));
}
__device__ __forceinline__ void ldmx4(uint32_t* r, uint32_t addr) {
    asm volatile(
        "ldmatrix.sync.aligned.m8n8.x4.shared.b16 {%0,%1,%2,%3}, [%4];"
        : "=r"(r[0]), "=r"(r[1]), "=r"(r[2]), "=r"(r[3]) : "r"(addr));
}
__device__ __forceinline__ uint32_t smem_u32(const void* p) {
    uint32_t a;
    asm("{ .reg .u64 t; cvta.to.shared.u64 t, %1; cvt.u32.u64 %0, t; }"
        : "=r"(a) : "l"(p));
    return a;
}

// ---------------------------------------------------------------------------
__global__ void build_M_kernel(const float* __restrict__ tw,
                               const float* __restrict__ wlin) {
    int q = blockIdx.x, p = cQP[q], kg = cQKG[q];
    __shared__ float twS[4096], wlS[4096];
    for (int i = threadIdx.x; i < 4096; i += blockDim.x) twS[i] = tw[p * 4096 + i];
    for (int i = threadIdx.x; i < 4096; i += blockDim.x) {
        int o = i >> 6, op = i & 63;
        wlS[o * 64 + op] = wlin[op * 1024 + o * 16 + kg];
    }
    __syncthreads();
    for (int r = threadIdx.x; r < 4096; r += blockDim.x) {
        int h = r >> 6, op = r & 63;
        float acc = 0.0f;
#pragma unroll 8
        for (int o = 0; o < 64; ++o) acc += twS[h * 64 + o] * wlS[o * 64 + op];
        g_Mh[q * 4096 + op * 64 + h] = __float2half_rn(acc);
    }
}

__global__ void init_out_kernel(float* __restrict__ out,
                                const float* __restrict__ b, int total) {
    int i = blockIdx.x * blockDim.x + threadIdx.x;
    if (i < total) out[i] = b[i & 63];
}

// ---------------------------------------------------------------------------
// SMEM layout (bytes), EPB=64 (identical footprint to R11): total 57344 B.
#define U_OFF   28672
#define M_OFF   38912
#define Y_OFF   49152
#define A_OFF   53248
#define IDX_OFF 56832
#define SMEM_TOTAL 57344

#define U_STRIDE 40
#define M_STRIDE 40
#define U_QSZ (EPB * U_STRIDE)   // 2560 halves = 5120 B
#define M_QSZ (64 * M_STRIDE)    // 2560 halves = 5120 B

__global__ __launch_bounds__(NTHREADS, 4)
void edge_kernel(const float* __restrict__ nf, const float* __restrict__ ev,
                 const int* __restrict__ ei, const float* __restrict__ cg,
                 float* __restrict__ out, int E) {
    extern __shared__ char smx[];
    __half* sSrc = (__half*)smx;
    __half* sU = (__half*)(smx + U_OFF);
    __half* sM = (__half*)(smx + M_OFF);
    float* sY = (float*)(smx + Y_OFF);
    float* sAI = (float*)(smx + A_OFF);   // interleaved [ic][e][q0,q1]
    int* sIdx = (int*)(smx + IDX_OFF);
    const int tid = threadIdx.x;
    const int e0 = blockIdx.x * EPB;
    const uint32_t sb = smem_u32(smx);

    // ---- Y + indices ----
    if (tid < EPB) {
        int e = e0 + tid;
        if (e < E) {
            float x = ev[e * 3], y = ev[e * 3 + 1], z = ev[e * 3 + 2];
            float x2 = x * x, y2 = y * y, z2 = z * z;
            float Y[16];
            Y[0] = 0.28209479177387814f;
            Y[1] = 0.4886025119029199f * y;
            Y[2] = 0.4886025119029199f * z;
            Y[3] = 0.4886025119029199f * x;
            Y[4] = 1.0925484305920792f * x * y;
            Y[5] = 1.0925484305920792f * y * z;
            Y[6] = 0.31539156525252005f * (3.0f * z2 - 1.0f);
            Y[7] = 1.0925484305920792f * x * z;
            Y[8] = 0.5462742152960396f * (x2 - y2);
            Y[9] = 0.5900435899266435f * y * (3.0f * x2 - y2);
            Y[10] = 2.890611442640554f * x * y * z;
            Y[11] = 0.4570457994644658f * y * (5.0f * z2 - 1.0f);
            Y[12] = 0.3731763325901154f * z * (5.0f * z2 - 3.0f);
            Y[13] = 0.4570457994644658f * x * (5.0f * z2 - 1.0f);
            Y[14] = 1.445305721320277f * z * (x2 - y2);
            Y[15] = 0.5900435899266435f * x * (x2 - 3.0f * y2);
#pragma unroll
            for (int j = 0; j < 16; ++j) sY[j * EPB + tid] = Y[j];
            sIdx[tid] = ei[e];
            sIdx[EPB + tid] = ei[E + e];
        } else {
#pragma unroll
            for (int j = 0; j < 16; ++j) sY[j * EPB + tid] = 0.0f;
            sIdx[tid] = 0;
            sIdx[EPB + tid] = -1;
        }
    }

    // q-split warp mapping: warp = (qq, wx, wy2)
    const int lane = tid & 31, gid = lane >> 2, tig = lane & 3;
    const int wid = tid >> 5;
    const int qq = wid & 1;
    const int wx = (wid >> 1) & 1;
    const int wy2 = wid >> 2;
    float acc[2][4][4];
#pragma unroll
    for (int mt = 0; mt < 2; ++mt)
#pragma unroll
        for (int nt = 0; nt < 4; ++nt)
#pragma unroll
            for (int r = 0; r < 4; ++r) acc[mt][nt][r] = 0.0f;

    // ldmatrix per-lane base addresses (constant per warp/lane)
    // A: rows (wy2*32 + mt*16 + quadrant rows), quadrants: (r0-15,k0) (r0-15,k8)
    const uint32_t aFragBase = sb + U_OFF + qq * 5120 +
        (uint32_t)((wy2 * 32 + (lane & 15)) * 80 + (lane >> 4) * 16);
    // B: rows o' = wx*32 + nb*16 + quadrants (n0-7,k0)(n0-7,k8)(n8-15,k0)(n8-15,k8)
    const uint32_t bFragBase = sb + M_OFF + qq * 5120 +
        (uint32_t)((wx * 32 + (lane & 7) + (lane >> 4) * 8) * 80 +
                   ((lane >> 3) & 1) * 16);
    __syncthreads();

    for (int g = 0; g < 4; ++g) {
        const int nc = 2 * g + 1, i0 = g * g;
        for (int hlf = 0; hlf < 2; ++hlf) {
            // ---- gather sSrc[ic][e][hh] (vectorized over irreps) ----
            for (int idx = tid; idx < EPB * 32; idx += NTHREADS) {
                int e = idx >> 5, hh = idx & 31;
                const float* base =
                    nf + (size_t)sIdx[e] * 1024 + (hlf * 32 + hh) * 16;
                __half* d = sSrc + e * 32 + hh;  // + ic*2048
                if (g == 0) {
                    d[0] = __float2half_rn(__ldg(base));
                } else if (g == 1) {
                    float4 v = __ldg((const float4*)base);
                    d[0] = __float2half_rn(v.y);
                    d[2048] = __float2half_rn(v.z);
                    d[4096] = __float2half_rn(v.w);
                } else if (g == 2) {
                    float4 v = __ldg((const float4*)(base + 4));
                    float s = __ldg(base + 8);
                    d[0] = __float2half_rn(v.x);
                    d[2048] = __float2half_rn(v.y);
                    d[4096] = __float2half_rn(v.z);
                    d[6144] = __float2half_rn(v.w);
                    d[8192] = __float2half_rn(s);
                } else {
                    float4 va = __ldg((const float4*)(base + 8));
                    float4 vb = __ldg((const float4*)(base + 12));
                    d[0] = __float2half_rn(va.y);
                    d[2048] = __float2half_rn(va.z);
                    d[4096] = __float2half_rn(va.w);
                    d[6144] = __float2half_rn(vb.x);
                    d[8192] = __float2half_rn(vb.y);
                    d[10240] = __float2half_rn(vb.z);
                    d[12288] = __float2half_rn(vb.w);
                }
            }
            __syncthreads();

            const int qend = cPSTART[g + 1];
            for (int qb = cPSTART[g]; qb < qend; qb += 2) {
                const int nqc = (qend - qb >= 2) ? 2 : 1;

                // ---- phase A: A-coeffs -> interleaved sAI + M tile copy ----
                for (int idx = tid; idx < nqc * nc * EPB; idx += NTHREADS) {
                    int e = idx & 63, r = idx >> 6;
                    int ic = r % nc, qi = r / nc, q = qb + qi;
                    int j0 = cQJ0[q], kg = cQKG[q];
                    int nj = (j0 == 0) ? 1 : (j0 == 1) ? 3 : (j0 == 4) ? 5 : 7;
                    const float* cgp = cg + (i0 + ic) * 256 + j0 * 16 + kg;
                    float a = 0.0f;
#pragma unroll
                    for (int jc = 0; jc < 7; ++jc)
                        if (jc < nj) a += sY[(j0 + jc) * EPB + e] * __ldg(cgp + jc * 16);
                    sAI[(ic * EPB + e) * 2 + qi] = a;
                }
                for (int idx = tid; idx < nqc * 256; idx += NTHREADS) {
                    int qi = idx >> 8, w = idx & 255;
                    int o = w >> 2, seg = w & 3;
                    uint4 v = *(const uint4*)(g_Mh + (qb + qi) * 4096 + o * 64 +
                                              hlf * 32 + seg * 8);
                    *(uint4*)(sM + qi * M_QSZ + o * M_STRIDE + seg * 8) = v;
                }
                __syncthreads();

                // ---- phase B: U tiles (fp32 math, fp16 store) ----
                for (int idx = tid; idx < EPB * 8; idx += NTHREADS) {
                    int e = idx >> 3, hv = idx & 7;
                    float u0[4] = {0, 0, 0, 0}, u1[4] = {0, 0, 0, 0};
#pragma unroll
                    for (int ic = 0; ic < 7; ++ic)
                        if (ic < nc) {
                            uint2 sw = *(const uint2*)(sSrc + ic * 2048 +
                                                       e * 32 + hv * 4);
                            float2 f0 = __half22float2(*(__half2*)&sw.x);
                            float2 f1 = __half22float2(*(__half2*)&sw.y);
                            float2 a2 = *(const float2*)&sAI[(ic * EPB + e) * 2];
                            u0[0] += a2.x * f0.x; u0[1] += a2.x * f0.y;
                            u0[2] += a2.x * f1.x; u0[3] += a2.x * f1.y;
                            if (nqc == 2) {
                                u1[0] += a2.y * f0.x; u1[1] += a2.y * f0.y;
                                u1[2] += a2.y * f1.x; u1[3] += a2.y * f1.y;
                            }
                        }
                    {
                        __half2 p0 = __floats2half2_rn(u0[0], u0[1]);
                        __half2 p1 = __floats2half2_rn(u0[2], u0[3]);
                        uint2 st = {*(uint32_t*)&p0, *(uint32_t*)&p1};
                        *(uint2*)(sU + e * U_STRIDE + hv * 4) = st;
                    }
                    if (nqc == 2) {
                        __half2 p0 = __floats2half2_rn(u1[0], u1[1]);
                        __half2 p1 = __floats2half2_rn(u1[2], u1[3]);
                        uint2 st = {*(uint32_t*)&p0, *(uint32_t*)&p1};
                        *(uint2*)(sU + U_QSZ + e * U_STRIDE + hv * 4) = st;
                    }
                }
                __syncthreads();

                // ---- mma phase: warp owns ONE q; ldmatrix fragments ----
                if (qq < nqc) {
#pragma unroll
                    for (int ks = 0; ks < 2; ++ks) {
                        uint32_t aF0[4], aF1[4], bF0[4], bF1[4];
                        ldmx4(aF0, aFragBase + ks * 32);            // rows 0-15
                        ldmx4(aF1, aFragBase + ks * 32 + 16 * 80);  // rows 16-31
                        ldmx4(bF0, bFragBase + ks * 32);            // o' 0-15
                        ldmx4(bF1, bFragBase + ks * 32 + 16 * 80);  // o' 16-31
                        mma16(acc[0][0], aF0, bF0[0], bF0[1]);
                        mma16(acc[0][1], aF0, bF0[2], bF0[3]);
                        mma16(acc[0][2], aF0, bF1[0], bF1[1]);
                        mma16(acc[0][3], aF0, bF1[2], bF1[3]);
                        mma16(acc[1][0], aF1, bF0[0], bF0[1]);
                        mma16(acc[1][1], aF1, bF0[2], bF0[3]);
                        mma16(acc[1][2], aF1, bF1[0], bF1[1]);
                        mma16(acc[1][3], aF1, bF1[2], bF1[3]);
                    }
                }
                __syncthreads();
            }
        }
    }

    // ---- cross-q reduction: qq=1 warps dump acc, qq=0 warps add ----
    {
        float* sRed = (float*)smx;   // 4 tiles x 32x32 f32 = 16KB (sSrc dead)
        float* tile = sRed + (wy2 * 2 + wx) * 1024;
        if (qq == 1) {
#pragma unroll
            for (int mt = 0; mt < 2; ++mt)
#pragma unroll
                for (int nt = 0; nt < 4; ++nt)
#pragma unroll
                    for (int r = 0; r < 4; ++r) {
                        int row = mt * 16 + gid + (r >> 1) * 8;
                        int col = nt * 8 + tig * 2 + (r & 1);
                        tile[row * 32 + col] = acc[mt][nt][r];
                    }
        }
        __syncthreads();
        if (qq == 0) {
#pragma unroll
            for (int mt = 0; mt < 2; ++mt)
#pragma unroll
                for (int nt = 0; nt < 4; ++nt)
#pragma unroll
                    for (int r = 0; r < 4; ++r) {
                        int row = mt * 16 + gid + (r >> 1) * 8;
                        int col = nt * 8 + tig * 2 + (r & 1);
                        acc[mt][nt][r] += tile[row * 32 + col];
                    }
            // ---- epilogue: float2 atomics into out[dst] ----
#pragma unroll
            for (int mt = 0; mt < 2; ++mt)
#pragma unroll
                for (int r = 0; r < 2; ++r) {
                    int e = wy2 * 32 + mt * 16 + gid + r * 8;
                    int dst = sIdx[EPB + e];
                    if (dst >= 0) {
                        float* op = out + (size_t)dst * 64 + wx * 32 + 2 * tig;
#pragma unroll
                        for (int nt = 0; nt < 4; ++nt) {
                            float2 v = make_float2(acc[mt][nt][r * 2],
                                                   acc[mt][nt][r * 2 + 1]);
                            atomicAdd((float2*)(op + nt * 8), v);
                        }
                    }
                }
        }
    }
}

// ---------------------------------------------------------------------------
extern "C" void kernel_launch(void* const* d_in, const int* in_sizes, int n_in,
                              void* d_out, int out_size) {
    const float* nf = (const float*)d_in[0];
    const float* ev = (const float*)d_in[1];
    const int* ei = (const int*)d_in[2];
    const float* cg = (const float*)d_in[3];
    const float* tw = (const float*)d_in[4];
    const float* wlin = (const float*)d_in[5];
    const float* bl = (const float*)d_in[6];
    float* out = (float*)d_out;
    const int E = in_sizes[1] / 3;
    const int N = in_sizes[0] / 1024;

    cudaFuncSetAttribute(edge_kernel,
                         cudaFuncAttributeMaxDynamicSharedMemorySize, SMEM_TOTAL);
    build_M_kernel<<<Q_TOTAL, 256>>>(tw, wlin);
    init_out_kernel<<<(N * 64 + 255) / 256, 256>>>(out, bl, N * 64);
    edge_kernel<<<(E + EPB - 1) / EPB, NTHREADS, SMEM_TOTAL>>>(nf, ev, ei, cg, out, E);
}